// round 3
// baseline (speedup 1.0000x reference)
#include <cuda_runtime.h>

#define HID   128
#define NSTEP 128
#define MROWS 16
#define HSTR  20      // smem activation row stride (floats), [k][m] layout
#define NEGS  0.2f

typedef unsigned long long u64;

// ---------- packed fp32x2 helpers (Blackwell sm_100+) ----------
__device__ __forceinline__ u64 ffma2(u64 x, u64 y, u64 c) {
    u64 d;
    asm("fma.rn.f32x2 %0, %1, %2, %3;" : "=l"(d) : "l"(x), "l"(y), "l"(c));
    return d;
}
__device__ __forceinline__ u64 pack2(float lo, float hi) {
    u64 d;
    asm("mov.b64 %0, {%1, %2};" : "=l"(d) : "f"(lo), "f"(hi));
    return d;
}
__device__ __forceinline__ void unpack2(u64 v, float& lo, float& hi) {
    asm("mov.b64 {%0, %1}, %2;" : "=f"(lo), "=f"(hi) : "l"(v));
}

// Accumulators: [jp][mm] -> value pair = (out[j0+2jp][m0+mm], out[j0+2jp+1][m0+mm])
struct Acc4 { u64 a[2][2]; };

__device__ __forceinline__ void acc_zero(Acc4& A) {
    A.a[0][0] = 0ull; A.a[0][1] = 0ull; A.a[1][0] = 0ull; A.a[1][1] = 0ull;
}

// out[j][m] += sum_k hin[k][m] * W[k][j], K = HID.
// Thread covers j0..j0+3 (quad) x m0..m0+1 (pair). hin layout: [k][m], stride HSTR.
__device__ __forceinline__ void mm_pass(Acc4& A, const float* __restrict__ W,
                                        const float* __restrict__ hin,
                                        int j0, int m0) {
#pragma unroll 16
    for (int k = 0; k < HID; ++k) {
        const float4 w  = __ldg(reinterpret_cast<const float4*>(W + k * HID + j0));
        const float2 av = *reinterpret_cast<const float2*>(hin + k * HSTR + m0);
        // w01/w23 are natural register pairs from the LDG.128 — ptxas can elide these movs
        u64 w01 = pack2(w.x, w.y);
        u64 w23 = pack2(w.z, w.w);
        u64 a0  = pack2(av.x, av.x);   // duplicate activation for both j's of the pair
        u64 a1  = pack2(av.y, av.y);
        A.a[0][0] = ffma2(w01, a0, A.a[0][0]);
        A.a[0][1] = ffma2(w01, a1, A.a[0][1]);
        A.a[1][0] = ffma2(w23, a0, A.a[1][0]);
        A.a[1][1] = ffma2(w23, a1, A.a[1][1]);
    }
}

// bias + (optional residual) + LeakyReLU, store into hout[k=j][m]
template <bool RES>
__device__ __forceinline__ void epi(const Acc4& A, const float* __restrict__ bias,
                                    float* __restrict__ hout,
                                    const float* __restrict__ hres,
                                    int j0, int m0) {
    const float4 b4 = __ldg(reinterpret_cast<const float4*>(bias + j0));
    const float bb[4] = {b4.x, b4.y, b4.z, b4.w};
#pragma unroll
    for (int jp = 0; jp < 2; ++jp) {
#pragma unroll
        for (int mm = 0; mm < 2; ++mm) {
            float vlo, vhi;
            unpack2(A.a[jp][mm], vlo, vhi);
            float x0 = vlo + bb[2 * jp];
            float x1 = vhi + bb[2 * jp + 1];
            if (RES) {
                x0 += hres[(j0 + 2 * jp) * HSTR + m0 + mm];
                x1 += hres[(j0 + 2 * jp + 1) * HSTR + m0 + mm];
            }
            x0 = fmaxf(x0, NEGS * x0);   // leaky(x) = max(x, 0.2x)
            x1 = fmaxf(x1, NEGS * x1);
            hout[(j0 + 2 * jp) * HSTR + m0 + mm] = x0;
            hout[(j0 + 2 * jp + 1) * HSTR + m0 + mm] = x1;
        }
    }
}

template <bool RES>
__device__ __forceinline__ void full_layer(const float* __restrict__ W,
                                           const float* __restrict__ b,
                                           const float* __restrict__ hin,
                                           float* __restrict__ hout,
                                           const float* __restrict__ hres,
                                           int j0, int m0) {
    Acc4 A; acc_zero(A);
    mm_pass(A, W, hin, j0, m0);
    epi<RES>(A, b, hout, hres, j0, m0);
}

// Small-K input layer: reads raw features xs[m][12] at column offset coff.
__device__ __forceinline__ void input_layer(const float* __restrict__ Win,
                                            const float* __restrict__ bin,
                                            const float* __restrict__ xs,
                                            int coff, int K,
                                            float* __restrict__ hout,
                                            int j0, int m0) {
    float acc[4][2] = {};
    for (int k = 0; k < K; ++k) {
        const float4 w = __ldg(reinterpret_cast<const float4*>(Win + k * HID + j0));
        const float a0 = xs[(m0 + 0) * 12 + coff + k];
        const float a1 = xs[(m0 + 1) * 12 + coff + k];
        acc[0][0] = fmaf(w.x, a0, acc[0][0]); acc[0][1] = fmaf(w.x, a1, acc[0][1]);
        acc[1][0] = fmaf(w.y, a0, acc[1][0]); acc[1][1] = fmaf(w.y, a1, acc[1][1]);
        acc[2][0] = fmaf(w.z, a0, acc[2][0]); acc[2][1] = fmaf(w.z, a1, acc[2][1]);
        acc[3][0] = fmaf(w.w, a0, acc[3][0]); acc[3][1] = fmaf(w.w, a1, acc[3][1]);
    }
    const float4 b4 = __ldg(reinterpret_cast<const float4*>(bin + j0));
    const float bb[4] = {b4.x, b4.y, b4.z, b4.w};
#pragma unroll
    for (int jj = 0; jj < 4; ++jj) {
#pragma unroll
        for (int mm = 0; mm < 2; ++mm) {
            float x = acc[jj][mm] + bb[jj];
            x = fmaxf(x, NEGS * x);
            hout[(j0 + jj) * HSTR + m0 + mm] = x;
        }
    }
}

__global__ void __launch_bounds__(256, 1)
hedger_kernel(const float* __restrict__ feats,
              const float* __restrict__ fw_in, const float* __restrict__ fb_in,
              const float* __restrict__ fr1_w1, const float* __restrict__ fr1_b1,
              const float* __restrict__ fr1_w2, const float* __restrict__ fr1_b2,
              const float* __restrict__ fr2_w1, const float* __restrict__ fr2_b1,
              const float* __restrict__ fr2_w2, const float* __restrict__ fr2_b2,
              const float* __restrict__ pw_in, const float* __restrict__ pb_in,
              const float* __restrict__ pr1_w1, const float* __restrict__ pr1_b1,
              const float* __restrict__ pr1_w2, const float* __restrict__ pr1_b2,
              const float* __restrict__ pr2_w1, const float* __restrict__ pr2_b1,
              const float* __restrict__ pr2_w2, const float* __restrict__ pr2_b2,
              const float* __restrict__ cw1, const float* __restrict__ cb1,
              const float* __restrict__ cw2, const float* __restrict__ cb2,
              float* __restrict__ out) {
    // Activations live in SMEM transposed: h[k][m], k = feature 0..127, m = row 0..15
    __shared__ float hb_f[HID * HSTR];   // flat tower block input / tower state
    __shared__ float ht_f[HID * HSTR];   // flat tower temp (also combiner output)
    __shared__ float hb_p[HID * HSTR];   // path tower state
    __shared__ float ht_p[HID * HSTR];   // path tower temp
    __shared__ float xs[MROWS * 12];     // raw features for this step
    __shared__ float delta_s[MROWS];     // recurrent delta

    const int tid  = threadIdx.x;
    const int lane = tid & 31;
    const int warp = tid >> 5;
    const int j0 = (warp & 3) * 32 + (lane & 7) * 4;        // j-quad
    const int m0 = (warp >> 2) * 8 + (lane >> 3) * 2;       // m-pair
    const int b0 = blockIdx.x * MROWS;

    const float cb2v = __ldg(cb2);

    for (int n = 0; n < NSTEP; ++n) {
        // ---- load this step's features; substitute recurrent delta into col 3 ----
        if (tid < MROWS * 12) {
            const int r = tid / 12, c = tid % 12;
            float v = feats[((size_t)(b0 + r) * NSTEP + n) * 12 + c];
            if (c == 3 && n > 0) v = delta_s[r];
            xs[tid] = v;
        }
        __syncthreads();

        // ---- input layers (flat K=4, path K=8) ----
        input_layer(fw_in, fb_in, xs, 0, 4, hb_f, j0, m0);
        input_layer(pw_in, pb_in, xs, 4, 8, hb_p, j0, m0);
        __syncthreads();

        // ---- flat tower: 2 residual blocks ----
        full_layer<false>(fr1_w1, fr1_b1, hb_f, ht_f, nullptr, j0, m0); __syncthreads();
        full_layer<true >(fr1_w2, fr1_b2, ht_f, hb_f, hb_f,    j0, m0); __syncthreads();
        full_layer<false>(fr2_w1, fr2_b1, hb_f, ht_f, nullptr, j0, m0); __syncthreads();
        full_layer<true >(fr2_w2, fr2_b2, ht_f, hb_f, hb_f,    j0, m0); __syncthreads();

        // ---- path tower: 2 residual blocks ----
        full_layer<false>(pr1_w1, pr1_b1, hb_p, ht_p, nullptr, j0, m0); __syncthreads();
        full_layer<true >(pr1_w2, pr1_b2, ht_p, hb_p, hb_p,    j0, m0); __syncthreads();
        full_layer<false>(pr2_w1, pr2_b1, hb_p, ht_p, nullptr, j0, m0); __syncthreads();
        full_layer<true >(pr2_w2, pr2_b2, ht_p, hb_p, hb_p,    j0, m0); __syncthreads();

        // ---- combiner: concat(fe, pe) @ cw1 + cb1, leaky -> ht_f ----
        {
            Acc4 A; acc_zero(A);
            mm_pass(A, cw1,             hb_f, j0, m0);   // rows 0..127   (fe)
            mm_pass(A, cw1 + HID * HID, hb_p, j0, m0);   // rows 128..255 (pe)
            epi<false>(A, cb1, ht_f, nullptr, j0, m0);
        }
        __syncthreads();

        // ---- head: sigmoid(hc @ cw2 + cb2) -> delta, write output ----
        {
            const int m = tid >> 4;          // 0..15
            const int seg = tid & 15;        // 16-way split of j
            float p = 0.0f;
#pragma unroll
            for (int jj = 0; jj < 8; ++jj) {
                const int j = seg * 8 + jj;
                p += ht_f[j * HSTR + m] * __ldg(cw2 + j);
            }
            p += __shfl_down_sync(0xffffffffu, p, 8, 16);
            p += __shfl_down_sync(0xffffffffu, p, 4, 16);
            p += __shfl_down_sync(0xffffffffu, p, 2, 16);
            p += __shfl_down_sync(0xffffffffu, p, 1, 16);
            if (seg == 0) {
                const float d = 1.0f / (1.0f + expf(-(p + cb2v)));
                delta_s[m] = d;
                out[(size_t)(b0 + m) * NSTEP + n] = d;
            }
        }
        __syncthreads();
    }
}

extern "C" void kernel_launch(void* const* d_in, const int* in_sizes, int n_in,
                              void* d_out, int out_size) {
    const float* feats  = (const float*)d_in[0];
    const float* fw_in  = (const float*)d_in[1];
    const float* fb_in  = (const float*)d_in[2];
    const float* fr1_w1 = (const float*)d_in[3];
    const float* fr1_b1 = (const float*)d_in[4];
    const float* fr1_w2 = (const float*)d_in[5];
    const float* fr1_b2 = (const float*)d_in[6];
    const float* fr2_w1 = (const float*)d_in[7];
    const float* fr2_b1 = (const float*)d_in[8];
    const float* fr2_w2 = (const float*)d_in[9];
    const float* fr2_b2 = (const float*)d_in[10];
    const float* pw_in  = (const float*)d_in[11];
    const float* pb_in  = (const float*)d_in[12];
    const float* pr1_w1 = (const float*)d_in[13];
    const float* pr1_b1 = (const float*)d_in[14];
    const float* pr1_w2 = (const float*)d_in[15];
    const float* pr1_b2 = (const float*)d_in[16];
    const float* pr2_w1 = (const float*)d_in[17];
    const float* pr2_b1 = (const float*)d_in[18];
    const float* pr2_w2 = (const float*)d_in[19];
    const float* pr2_b2 = (const float*)d_in[20];
    const float* cw1    = (const float*)d_in[21];
    const float* cb1    = (const float*)d_in[22];
    const float* cw2    = (const float*)d_in[23];
    const float* cb2    = (const float*)d_in[24];

    hedger_kernel<<<2048 / MROWS, 256>>>(
        feats,
        fw_in, fb_in,
        fr1_w1, fr1_b1, fr1_w2, fr1_b2,
        fr2_w1, fr2_b1, fr2_w2, fr2_b2,
        pw_in, pb_in,
        pr1_w1, pr1_b1, pr1_w2, pr1_b2,
        pr2_w1, pr2_b1, pr2_w2, pr2_b2,
        cw1, cb1, cw2, cb2,
        (float*)d_out);
}

// round 4
// speedup vs baseline: 1.5357x; 1.5357x over previous
#include <cuda_runtime.h>

#define HID   128
#define NSTEP 128
#define MROWS 16
#define HSTR  20      // smem activation row stride (floats), [k][m] layout
#define NEGS  0.2f

// dynamic smem layout (float offsets)
#define WB0   0
#define WB1   16384
#define HBF   32768
#define HTF   (HBF + HID * HSTR)
#define HBP   (HTF + HID * HSTR)
#define HTP   (HBP + HID * HSTR)
#define XSO   (HTP + HID * HSTR)
#define DSO   (XSO + MROWS * 12)
#define SMEM_FLOATS (DSO + MROWS)
#define SMEM_BYTES  (SMEM_FLOATS * 4)

typedef unsigned long long u64;

// ---------- packed fp32x2 helpers (Blackwell sm_100+) ----------
__device__ __forceinline__ u64 ffma2(u64 x, u64 y, u64 c) {
    u64 d;
    asm("fma.rn.f32x2 %0, %1, %2, %3;" : "=l"(d) : "l"(x), "l"(y), "l"(c));
    return d;
}
__device__ __forceinline__ u64 pack2(float lo, float hi) {
    u64 d;
    asm("mov.b64 %0, {%1, %2};" : "=l"(d) : "f"(lo), "f"(hi));
    return d;
}
__device__ __forceinline__ void unpack2(u64 v, float& lo, float& hi) {
    asm("mov.b64 {%0, %1}, %2;" : "=f"(lo), "=f"(hi) : "l"(v));
}

// ---------- cp.async (weights -> smem staging) ----------
__device__ __forceinline__ void cp_async16(unsigned dst, const void* src) {
    asm volatile("cp.async.cg.shared.global [%0], [%1], 16;" :: "r"(dst), "l"(src));
}
__device__ __forceinline__ void cp_commit() {
    asm volatile("cp.async.commit_group;" ::: "memory");
}
__device__ __forceinline__ void cp_wait_all() {
    asm volatile("cp.async.wait_group 0;" ::: "memory");
}

// Copy one 64KB weight matrix (128x128 f32) global -> smem, fully coalesced.
__device__ __forceinline__ void prefetch_w(const float* __restrict__ src,
                                           float* dstf, int tid) {
    unsigned dst = (unsigned)__cvta_generic_to_shared(dstf);
#pragma unroll
    for (int i = 0; i < 16; ++i) {
        const int off = (tid + i * 256) * 16;   // bytes
        cp_async16(dst + off, (const char*)src + off);
    }
}

// Accumulators: [jp][mm] -> pair = (out[j0+2jp][m0+mm], out[j0+2jp+1][m0+mm])
struct Acc4 { u64 a[2][2]; };
__device__ __forceinline__ void acc_zero(Acc4& A) {
    A.a[0][0] = 0ull; A.a[0][1] = 0ull; A.a[1][0] = 0ull; A.a[1][1] = 0ull;
}

// out[j][m] += sum_k hin[k][m] * W[k][j]; W in SMEM (row stride HID floats).
// Lanes 0-7 of each LDS phase share one weight address (pure broadcast).
__device__ __forceinline__ void mm_pass(Acc4& A, const float* __restrict__ Wsm,
                                        const float* __restrict__ hin,
                                        int j0, int m0) {
#pragma unroll 8
    for (int k = 0; k < HID; ++k) {
        const float4 w  = *reinterpret_cast<const float4*>(Wsm + k * HID + j0);
        const float2 av = *reinterpret_cast<const float2*>(hin + k * HSTR + m0);
        u64 w01 = pack2(w.x, w.y);
        u64 w23 = pack2(w.z, w.w);
        u64 a0  = pack2(av.x, av.x);
        u64 a1  = pack2(av.y, av.y);
        A.a[0][0] = ffma2(w01, a0, A.a[0][0]);
        A.a[0][1] = ffma2(w01, a1, A.a[0][1]);
        A.a[1][0] = ffma2(w23, a0, A.a[1][0]);
        A.a[1][1] = ffma2(w23, a1, A.a[1][1]);
    }
}

// bias + (optional residual) + LeakyReLU -> hout[j][m]
template <bool RES>
__device__ __forceinline__ void epi(const Acc4& A, const float* __restrict__ bias,
                                    float* __restrict__ hout,
                                    const float* __restrict__ hres,
                                    int j0, int m0) {
    const float4 b4 = __ldg(reinterpret_cast<const float4*>(bias + j0));
    const float bb[4] = {b4.x, b4.y, b4.z, b4.w};
#pragma unroll
    for (int jp = 0; jp < 2; ++jp) {
#pragma unroll
        for (int mm = 0; mm < 2; ++mm) {
            float vlo, vhi;
            unpack2(A.a[jp][mm], vlo, vhi);
            float x0 = vlo + bb[2 * jp];
            float x1 = vhi + bb[2 * jp + 1];
            if (RES) {
                x0 += hres[(j0 + 2 * jp) * HSTR + m0 + mm];
                x1 += hres[(j0 + 2 * jp + 1) * HSTR + m0 + mm];
            }
            x0 = fmaxf(x0, NEGS * x0);
            x1 = fmaxf(x1, NEGS * x1);
            hout[(j0 + 2 * jp) * HSTR + m0 + mm] = x0;
            hout[(j0 + 2 * jp + 1) * HSTR + m0 + mm] = x1;
        }
    }
}

template <bool RES>
__device__ __forceinline__ void full_layer(const float* __restrict__ Wsm,
                                           const float* __restrict__ b,
                                           const float* __restrict__ hin,
                                           float* __restrict__ hout,
                                           const float* __restrict__ hres,
                                           int j0, int m0) {
    Acc4 A; acc_zero(A);
    mm_pass(A, Wsm, hin, j0, m0);
    epi<RES>(A, b, hout, hres, j0, m0);
}

// Small-K input layer: raw features xs[m][12] at column offset coff (weights via L1).
__device__ __forceinline__ void input_layer(const float* __restrict__ Win,
                                            const float* __restrict__ bin,
                                            const float* __restrict__ xs,
                                            int coff, int K,
                                            float* __restrict__ hout,
                                            int j0, int m0) {
    float acc[4][2] = {};
    for (int k = 0; k < K; ++k) {
        const float4 w = __ldg(reinterpret_cast<const float4*>(Win + k * HID + j0));
        const float a0 = xs[(m0 + 0) * 12 + coff + k];
        const float a1 = xs[(m0 + 1) * 12 + coff + k];
        acc[0][0] = fmaf(w.x, a0, acc[0][0]); acc[0][1] = fmaf(w.x, a1, acc[0][1]);
        acc[1][0] = fmaf(w.y, a0, acc[1][0]); acc[1][1] = fmaf(w.y, a1, acc[1][1]);
        acc[2][0] = fmaf(w.z, a0, acc[2][0]); acc[2][1] = fmaf(w.z, a1, acc[2][1]);
        acc[3][0] = fmaf(w.w, a0, acc[3][0]); acc[3][1] = fmaf(w.w, a1, acc[3][1]);
    }
    const float4 b4 = __ldg(reinterpret_cast<const float4*>(bin + j0));
    const float bb[4] = {b4.x, b4.y, b4.z, b4.w};
#pragma unroll
    for (int jj = 0; jj < 4; ++jj) {
#pragma unroll
        for (int mm = 0; mm < 2; ++mm) {
            float x = acc[jj][mm] + bb[jj];
            x = fmaxf(x, NEGS * x);
            hout[(j0 + jj) * HSTR + m0 + mm] = x;
        }
    }
}

__global__ void __launch_bounds__(256, 1)
hedger_kernel(const float* __restrict__ feats,
              const float* __restrict__ fw_in, const float* __restrict__ fb_in,
              const float* __restrict__ fr1_w1, const float* __restrict__ fr1_b1,
              const float* __restrict__ fr1_w2, const float* __restrict__ fr1_b2,
              const float* __restrict__ fr2_w1, const float* __restrict__ fr2_b1,
              const float* __restrict__ fr2_w2, const float* __restrict__ fr2_b2,
              const float* __restrict__ pw_in, const float* __restrict__ pb_in,
              const float* __restrict__ pr1_w1, const float* __restrict__ pr1_b1,
              const float* __restrict__ pr1_w2, const float* __restrict__ pr1_b2,
              const float* __restrict__ pr2_w1, const float* __restrict__ pr2_b1,
              const float* __restrict__ pr2_w2, const float* __restrict__ pr2_b2,
              const float* __restrict__ cw1, const float* __restrict__ cb1,
              const float* __restrict__ cw2, const float* __restrict__ cb2,
              float* __restrict__ out) {
    extern __shared__ float sm[];
    float* wb0  = sm + WB0;
    float* wb1  = sm + WB1;
    float* hb_f = sm + HBF;
    float* ht_f = sm + HTF;
    float* hb_p = sm + HBP;
    float* ht_p = sm + HTP;
    float* xs   = sm + XSO;
    float* ds   = sm + DSO;

    const int tid  = threadIdx.x;
    const int lane = tid & 31;
    const int warp = tid >> 5;
    // lanes 0-7 of each LDS phase share a j-quad (weight broadcast);
    // m-pairs vary within the phase (contiguous activation reads).
    const int j0 = warp * 16 + (lane >> 3) * 4;
    const int m0 = (lane & 7) * 2;
    const int b0 = blockIdx.x * MROWS;

    const float cb2v = __ldg(cb2);
    const float* cw1_hi = cw1 + HID * HID;

    // prologue: stage first big matrix
    prefetch_w(fr1_w1, wb0, tid);
    cp_commit();

    for (int n = 0; n < NSTEP; ++n) {
        // ---- features for this step; recurrent delta into col 3 ----
        if (tid < MROWS * 12) {
            const int r = tid / 12, c = tid % 12;
            float v = feats[((size_t)(b0 + r) * NSTEP + n) * 12 + c];
            if (c == 3 && n > 0) v = ds[r];
            xs[tid] = v;
        }
        __syncthreads();

        // ---- input layers (tiny K, weights L1-resident) ----
        input_layer(fw_in, fb_in, xs, 0, 4, hb_f, j0, m0);
        input_layer(pw_in, pb_in, xs, 4, 8, hb_p, j0, m0);

        // ---- 10 staged 64KB layers, double-buffered ----
        // L0: fr1_w1 (buf0), prefetch fr1_w2 -> buf1
        cp_wait_all(); __syncthreads();
        prefetch_w(fr1_w2, wb1, tid); cp_commit();
        full_layer<false>(wb0, fr1_b1, hb_f, ht_f, nullptr, j0, m0);

        // L1: fr1_w2 (buf1), prefetch fr2_w1 -> buf0
        cp_wait_all(); __syncthreads();
        prefetch_w(fr2_w1, wb0, tid); cp_commit();
        full_layer<true >(wb1, fr1_b2, ht_f, hb_f, hb_f, j0, m0);

        // L2
        cp_wait_all(); __syncthreads();
        prefetch_w(fr2_w2, wb1, tid); cp_commit();
        full_layer<false>(wb0, fr2_b1, hb_f, ht_f, nullptr, j0, m0);

        // L3
        cp_wait_all(); __syncthreads();
        prefetch_w(pr1_w1, wb0, tid); cp_commit();
        full_layer<true >(wb1, fr2_b2, ht_f, hb_f, hb_f, j0, m0);

        // L4
        cp_wait_all(); __syncthreads();
        prefetch_w(pr1_w2, wb1, tid); cp_commit();
        full_layer<false>(wb0, pr1_b1, hb_p, ht_p, nullptr, j0, m0);

        // L5
        cp_wait_all(); __syncthreads();
        prefetch_w(pr2_w1, wb0, tid); cp_commit();
        full_layer<true >(wb1, pr1_b2, ht_p, hb_p, hb_p, j0, m0);

        // L6
        cp_wait_all(); __syncthreads();
        prefetch_w(pr2_w2, wb1, tid); cp_commit();
        full_layer<false>(wb0, pr2_b1, hb_p, ht_p, nullptr, j0, m0);

        // L7
        cp_wait_all(); __syncthreads();
        prefetch_w(cw1, wb0, tid); cp_commit();
        full_layer<true >(wb1, pr2_b2, ht_p, hb_p, hb_p, j0, m0);

        // L8 + L9: combiner, accumulate across both halves
        Acc4 A; acc_zero(A);
        cp_wait_all(); __syncthreads();
        prefetch_w(cw1_hi, wb1, tid); cp_commit();
        mm_pass(A, wb0, hb_f, j0, m0);            // fe @ cw1[0:128]

        cp_wait_all(); __syncthreads();
        prefetch_w(fr1_w1, wb0, tid); cp_commit();  // wrap: next step's L0
        mm_pass(A, wb1, hb_p, j0, m0);            // pe @ cw1[128:256]
        epi<false>(A, cb1, ht_f, nullptr, j0, m0);
        __syncthreads();

        // ---- head: sigmoid(hc @ cw2 + cb2) ----
        {
            const int m = tid >> 4;          // 0..15
            const int seg = tid & 15;        // 16-way j split
            float p = 0.0f;
#pragma unroll
            for (int jj = 0; jj < 8; ++jj) {
                const int j = seg * 8 + jj;
                p += ht_f[j * HSTR + m] * __ldg(cw2 + j);
            }
            p += __shfl_down_sync(0xffffffffu, p, 8, 16);
            p += __shfl_down_sync(0xffffffffu, p, 4, 16);
            p += __shfl_down_sync(0xffffffffu, p, 2, 16);
            p += __shfl_down_sync(0xffffffffu, p, 1, 16);
            if (seg == 0) {
                const float d = 1.0f / (1.0f + expf(-(p + cb2v)));
                ds[m] = d;
                out[(size_t)(b0 + m) * NSTEP + n] = d;
            }
        }
        __syncthreads();
    }
}

extern "C" void kernel_launch(void* const* d_in, const int* in_sizes, int n_in,
                              void* d_out, int out_size) {
    const float* feats  = (const float*)d_in[0];
    const float* fw_in  = (const float*)d_in[1];
    const float* fb_in  = (const float*)d_in[2];
    const float* fr1_w1 = (const float*)d_in[3];
    const float* fr1_b1 = (const float*)d_in[4];
    const float* fr1_w2 = (const float*)d_in[5];
    const float* fr1_b2 = (const float*)d_in[6];
    const float* fr2_w1 = (const float*)d_in[7];
    const float* fr2_b1 = (const float*)d_in[8];
    const float* fr2_w2 = (const float*)d_in[9];
    const float* fr2_b2 = (const float*)d_in[10];
    const float* pw_in  = (const float*)d_in[11];
    const float* pb_in  = (const float*)d_in[12];
    const float* pr1_w1 = (const float*)d_in[13];
    const float* pr1_b1 = (const float*)d_in[14];
    const float* pr1_w2 = (const float*)d_in[15];
    const float* pr1_b2 = (const float*)d_in[16];
    const float* pr2_w1 = (const float*)d_in[17];
    const float* pr2_b1 = (const float*)d_in[18];
    const float* pr2_w2 = (const float*)d_in[19];
    const float* pr2_b2 = (const float*)d_in[20];
    const float* cw1    = (const float*)d_in[21];
    const float* cb1    = (const float*)d_in[22];
    const float* cw2    = (const float*)d_in[23];
    const float* cb2    = (const float*)d_in[24];

    cudaFuncSetAttribute(hedger_kernel,
                         cudaFuncAttributeMaxDynamicSharedMemorySize, SMEM_BYTES);

    hedger_kernel<<<2048 / MROWS, 256, SMEM_BYTES>>>(
        feats,
        fw_in, fb_in,
        fr1_w1, fr1_b1, fr1_w2, fr1_b2,
        fr2_w1, fr2_b1, fr2_w2, fr2_b2,
        pw_in, pb_in,
        pr1_w1, pr1_b1, pr1_w2, pr1_b2,
        pr2_w1, pr2_b1, pr2_w2, pr2_b2,
        cw1, cb1, cw2, cb2,
        (float*)d_out);
}